// round 14
// baseline (speedup 1.0000x reference)
#include <cuda_runtime.h>
#include <cuda_bf16.h>
#include <stdint.h>

#define Gx 106
#define G2x (106 * 106)
#define G3x (106 * 106 * 106)
#define MAXB 2
#define CROP 100
#define CROPV (100 * 100 * 100)

// Dual-parity scratch, float2 per slot = (grid_sum, acc_sum).
//   P0: cell c -> slot c            (even c 16B-aligned)
//   P1: cell c -> slot SHIFT + c    (odd  c 16B-aligned; SHIFT is odd)
#define SHIFT (MAXB * G3x + 1)
#define NSLOTS (2 * MAXB * G3x + 2)
__device__ float2 g_combo2[NSLOTS];

// ---------------------------------------------------------------------------
// Per-batch zero: two float4-aligned ranges (P0 slice, P1 slice incl. 1-slot
// even-alignment pad on each side; pad slots are out-of-crop / inter-region).
// ---------------------------------------------------------------------------
__global__ void __launch_bounds__(256)
splat_zero2_kernel(int sA2, int nA4, int sB2, int nB4) {
    int i = blockIdx.x * blockDim.x + threadIdx.x;
    float4* base = reinterpret_cast<float4*>(g_combo2);
    float4 z = make_float4(0.f, 0.f, 0.f, 0.f);
    if (i < nA4) {
        base[(sA2 >> 1) + i] = z;
    } else if (i < nA4 + nB4) {
        base[(sB2 >> 1) + (i - nA4)] = z;
    }
}

// ---------------------------------------------------------------------------
// Per-batch scatter: one thread per point. 4x4x4 window, 32 red.v4 per point.
// At the red lane-issue floor; per-point math bit-faithful to the reference.
// ---------------------------------------------------------------------------
__global__ void __launch_bounds__(256)
splat_scatter_kernel(const float* __restrict__ points,
                     const float* __restrict__ dens,
                     const float* __restrict__ bbox,
                     int Npb, int b) {
    int t = blockIdx.x * blockDim.x + threadIdx.x;
    if (t >= Npb) return;
    int p = b * Npb + t;

    float d = __ldg(dens + p);
    float px = __ldg(points + 3 * p + 0);
    float py = __ldg(points + 3 * p + 1);
    float pz = __ldg(points + 3 * p + 2);

    int lo[3];
    float w[3][4];

    // Grid axis a uses point coordinate (2 - a) and bbox row (2 - a)
    // (the reference reverses the last dim of both points and bbox).
#pragma unroll
    for (int a = 0; a < 3; a++) {
        float c = (a == 0) ? pz : ((a == 1) ? py : px);
        int bd = 2 - a;
        float blo  = __fsub_rn(bbox[bd * 2 + 0], 0.03f);   // pad = (KR+1)*CELL
        float bhi  = __fadd_rn(bbox[bd * 2 + 1], 0.03f);
        float span = __fsub_rn(bhi, blo);
        // pg = ((c - blo) - CELL/2) / span * G   (op-for-op, IEEE rn)
        float tt = __fsub_rn(__fsub_rn(c, blo), 0.005f);
        float pg = __fmul_rn(__fdiv_rn(tt, span), 106.0f);
        float pgr = rintf(pg);           // round-half-even == jnp.round
        int   gi  = (int)pgr;
        float frac = pg - pgr;           // Sterbenz-exact

        // Only one of offsets -2/+2 is nonzero -> 4-wide window.
        int l = (frac < 0.0f) ? -2 : -1;
        lo[a] = gi + l;
#pragma unroll
        for (int o = 0; o < 4; o++) {
            float dd = (float)(l + o) - frac;            // exact
            w[a][o] = fmaxf(1.0f - fabsf(dd) * 0.5f, 0.0f);
        }
    }

    float w20 = w[2][0], w21 = w[2][1], w22 = w[2][2], w23 = w[2][3];

    int c0 = b * G3x + lo[0] * G2x + lo[1] * Gx + lo[2];  // window-start cell
    int sh = lo[2] & 1;                                    // parity -> copy select
    float2* base = g_combo2 + ((size_t)c0 + (sh ? (size_t)SHIFT : (size_t)0));

#pragma unroll
    for (int i = 0; i < 4; i++) {
        float w0 = w[0][i];
#pragma unroll
        for (int j = 0; j < 4; j++) {
            float wij  = w0 * w[1][j];
            float wijd = wij * d;
            float2* pp = base + i * G2x + j * Gx;

            asm volatile("red.global.add.v4.f32 [%0], {%1, %2, %3, %4};"
                         :: "l"(pp),
                            "f"(wijd * w20), "f"(wij * w20),
                            "f"(wijd * w21), "f"(wij * w21)
                         : "memory");
            asm volatile("red.global.add.v4.f32 [%0], {%1, %2, %3, %4};"
                         :: "l"(pp + 2),
                            "f"(wijd * w22), "f"(wij * w22),
                            "f"(wijd * w23), "f"(wij * w23)
                         : "memory");
        }
    }
}

// ---------------------------------------------------------------------------
// Per-batch finalize: read-only crop, fast divide, float4 output stores.
// ---------------------------------------------------------------------------
__global__ void __launch_bounds__(256)
splat_finalize_kernel(float* __restrict__ out, int b, int tot, int writeAcc) {
    int q = blockIdx.x * blockDim.x + threadIdx.x;
    if (q >= (CROPV >> 2)) return;
    int ol = q << 2;                     // local offset within batch

    int i = ol / (CROP * CROP);
    int rem = ol - i * (CROP * CROP);
    int j = rem / CROP;
    int k = rem - j * CROP;              // multiple of 4

    int src = b * G3x + (i + 3) * G2x + (j + 3) * Gx + (k + 3);
    const float2* __restrict__ p0 = g_combo2 + src;
    const float2* __restrict__ p1 = g_combo2 + SHIFT + src;

    float4 go, ao;
#pragma unroll
    for (int u = 0; u < 4; u++) {
        float2 c0 = __ldg(p0 + u);
        float2 c1 = __ldg(p1 + u);
        float g = c0.x + c1.x;
        float a = c0.y + c1.y;
        float v = (a > 0.0f) ? __fdividef(g, a + 1e-9f) : g;
        if (u == 0) { go.x = v; ao.x = a; }
        if (u == 1) { go.y = v; ao.y = a; }
        if (u == 2) { go.z = v; ao.z = a; }
        if (u == 3) { go.w = v; ao.w = a; }
    }
    int o = b * CROPV + ol;
    *reinterpret_cast<float4*>(out + o) = go;
    if (writeAcc) *reinterpret_cast<float4*>(out + tot + o) = ao;
}

// ---------------------------------------------------------------------------
// Two-stream pipelined launch. Chain 0 on the capture (NULL) stream, chain 1
// on a NON-BLOCKING stream (no implicit legacy-stream sync -> the captured
// graph has genuinely parallel branches). Fork after zero0, join at the end.
// ---------------------------------------------------------------------------
extern "C" void kernel_launch(void* const* d_in, const int* in_sizes, int n_in,
                              void* d_out, int out_size) {
    const float* points = (const float*)d_in[0];
    const float* dens   = (const float*)d_in[1];
    const float* bbox   = (const float*)d_in[2];
    float* out = (float*)d_out;

    int total = in_sizes[1];              // B * N
    int B = total / 131072;
    if (B < 1) B = 1;
    if (B > MAXB) B = MAXB;
    int Npb = total / B;

    int tot = B * CROPV;
    int writeAcc = (out_size >= 2 * tot) ? 1 : 0;

    static cudaStream_t s1 = nullptr;
    static cudaEvent_t eFork = nullptr, eJoin = nullptr;
    if (s1 == nullptr) {
        cudaStreamCreateWithFlags(&s1, cudaStreamNonBlocking);   // key fix
        cudaEventCreateWithFlags(&eFork, cudaEventDisableTiming);
        cudaEventCreateWithFlags(&eJoin, cudaEventDisableTiming);
    }

    const int tpb = 256;
    // per-batch zero ranges (float2 start, float4 count), both starts even
    const int nA4 = G3x / 2;
    const int nB4 = (G3x + 2) / 2;
    const int zThreads = nA4 + nB4;
    const int zBlocks = (zThreads + tpb - 1) / tpb;
    const int sBlocks = (Npb + tpb - 1) / tpb;
    const int fBlocks = ((CROPV >> 2) + tpb - 1) / tpb;

    if (B == 2) {
        // batch 0 zero on the capture stream
        splat_zero2_kernel<<<zBlocks, tpb>>>(0, nA4, SHIFT - 1, nB4);
        cudaEventRecord(eFork, 0);
        // batch 1 chain on s1 (zero1 overlaps scatter0)
        cudaStreamWaitEvent(s1, eFork, 0);
        splat_zero2_kernel<<<zBlocks, tpb, 0, s1>>>(G3x, nA4, SHIFT - 1 + G3x, nB4);
        splat_scatter_kernel<<<sBlocks, tpb, 0, s1>>>(points, dens, bbox, Npb, 1);
        splat_finalize_kernel<<<fBlocks, tpb, 0, s1>>>(out, 1, tot, writeAcc);
        cudaEventRecord(eJoin, s1);
        // batch 0 chain continues on the capture stream
        splat_scatter_kernel<<<sBlocks, tpb>>>(points, dens, bbox, Npb, 0);
        splat_finalize_kernel<<<fBlocks, tpb>>>(out, 0, tot, writeAcc);
        // join
        cudaStreamWaitEvent(0, eJoin, 0);
    } else {
        // serial single-batch fallback
        splat_zero2_kernel<<<zBlocks, tpb>>>(0, nA4, SHIFT - 1, nB4);
        splat_scatter_kernel<<<sBlocks, tpb>>>(points, dens, bbox, Npb, 0);
        splat_finalize_kernel<<<fBlocks, tpb>>>(out, 0, tot, writeAcc);
    }
}

// round 15
// speedup vs baseline: 1.0451x; 1.0451x over previous
#include <cuda_runtime.h>
#include <cuda_bf16.h>
#include <stdint.h>

#define Gx 106
#define G2x (106 * 106)
#define G3x (106 * 106 * 106)
#define MAXB 2
#define CROP 100
#define CROPV (100 * 100 * 100)

// Dual-parity scratch, float2 per slot = (grid_sum, acc_sum).
//   P0: cell c -> slot c            (even c 16B-aligned)
//   P1: cell c -> slot SHIFT + c    (odd  c 16B-aligned; SHIFT is odd)
// Only cells with i in [3,102] are ever read by finalize; shells outside
// that range are scattered into but never read and never re-zeroed.
#define SHIFT (MAXB * G3x + 1)
#define NSLOTS (2 * MAXB * G3x + 2)
__device__ float2 g_combo2[NSLOTS];

// i-trimmed zero extent per batch/copy: cells [3*G2x, 103*G2x)
#define ZLEN   (100 * G2x)          // cells per trimmed slice (even)
#define ZOFF   (3 * G2x)            // slice start within a batch (even)

// ---------------------------------------------------------------------------
// Zero the readable scratch: 4 slices (2 batches x 2 parity copies).
// All slice starts even (P1 start padded down 1 never-read slot) -> float4.
// ---------------------------------------------------------------------------
__global__ void __launch_bounds__(256)
splat_zero_kernel(int nB) {
    int i = blockIdx.x * blockDim.x + threadIdx.x;
    int n4 = ZLEN / 2;                   // float4 per slice
    int slice = i / n4;                  // 0..4*nB-1 handled by grid size
    int off = i - slice * n4;
    if (slice >= 2 * nB) return;
    int b = slice >> 1;
    int par = slice & 1;
    // P0 slice start: b*G3x + ZOFF (even). P1: SHIFT-1 + b*G3x + ZOFF (even).
    int s2 = (par ? (SHIFT - 1) : 0) + b * G3x + ZOFF;
    reinterpret_cast<float4*>(g_combo2)[(s2 >> 1) + off] =
        make_float4(0.f, 0.f, 0.f, 0.f);
}

// ---------------------------------------------------------------------------
// Scatter: one thread per point. 4x4x4 window, exactly 32 red.v4 per point.
// Parity of the k window start selects the scratch copy -> always 16B aligned.
// Measured at the red lane-issue floor; closed — byte-identical to R9.
// ---------------------------------------------------------------------------
__global__ void __launch_bounds__(256)
splat_scatter_kernel(const float* __restrict__ points,
                     const float* __restrict__ dens,
                     const float* __restrict__ bbox,
                     int total, int Npb) {
    int t = blockIdx.x * blockDim.x + threadIdx.x;
    if (t >= total) return;

    int b = t / Npb;
    float d = __ldg(dens + t);

    float px = __ldg(points + 3 * t + 0);
    float py = __ldg(points + 3 * t + 1);
    float pz = __ldg(points + 3 * t + 2);

    int lo[3];
    float w[3][4];

    // Grid axis a uses point coordinate (2 - a) and bbox row (2 - a)
    // (the reference reverses the last dim of both points and bbox).
#pragma unroll
    for (int a = 0; a < 3; a++) {
        float c = (a == 0) ? pz : ((a == 1) ? py : px);
        int bd = 2 - a;
        float blo  = __fsub_rn(bbox[bd * 2 + 0], 0.03f);   // pad = (KR+1)*CELL
        float bhi  = __fadd_rn(bbox[bd * 2 + 1], 0.03f);
        float span = __fsub_rn(bhi, blo);
        // pg = ((c - blo) - CELL/2) / span * G   (op-for-op, IEEE rn)
        float tt = __fsub_rn(__fsub_rn(c, blo), 0.005f);
        float pg = __fmul_rn(__fdiv_rn(tt, span), 106.0f);
        float pgr = rintf(pg);           // round-half-even == jnp.round
        int   gi  = (int)pgr;
        float frac = pg - pgr;           // Sterbenz-exact

        // Only one of offsets -2/+2 is nonzero -> 4-wide window.
        int l = (frac < 0.0f) ? -2 : -1;
        lo[a] = gi + l;
#pragma unroll
        for (int o = 0; o < 4; o++) {
            float dd = (float)(l + o) - frac;            // exact
            w[a][o] = fmaxf(1.0f - fabsf(dd) * 0.5f, 0.0f);
        }
    }

    float w20 = w[2][0], w21 = w[2][1], w22 = w[2][2], w23 = w[2][3];

    int c0 = b * G3x + lo[0] * G2x + lo[1] * Gx + lo[2];  // window-start cell
    int sh = lo[2] & 1;                                    // parity -> copy select
    float2* base = g_combo2 + ((size_t)c0 + (sh ? (size_t)SHIFT : (size_t)0));

#pragma unroll
    for (int i = 0; i < 4; i++) {
        float w0 = w[0][i];
#pragma unroll
        for (int j = 0; j < 4; j++) {
            float wij  = w0 * w[1][j];
            float wijd = wij * d;
            float2* p = base + i * G2x + j * Gx;

            asm volatile("red.global.add.v4.f32 [%0], {%1, %2, %3, %4};"
                         :: "l"(p),
                            "f"(wijd * w20), "f"(wij * w20),
                            "f"(wijd * w21), "f"(wij * w21)
                         : "memory");
            asm volatile("red.global.add.v4.f32 [%0], {%1, %2, %3, %4};"
                         :: "l"(p + 2),
                            "f"(wijd * w22), "f"(wij * w22),
                            "f"(wijd * w23), "f"(wij * w23)
                         : "memory");
        }
    }
}

// ---------------------------------------------------------------------------
// Finalize: read-only over the CROP region. 4 k-cells per thread.
// Measured-best form (10us) — byte-identical to R9.
// ---------------------------------------------------------------------------
__global__ void __launch_bounds__(256)
splat_finalize_kernel(float* __restrict__ out, int B, int writeAcc) {
    int q = blockIdx.x * blockDim.x + threadIdx.x;
    int tot = B * CROPV;
    int tot4 = tot >> 2;
    if (q >= tot4) return;
    int o = q << 2;

    int b = o / CROPV;
    int r = o - b * CROPV;
    int i = r / (CROP * CROP);
    int rem = r - i * (CROP * CROP);
    int j = rem / CROP;
    int k = rem - j * CROP;            // multiple of 4

    int src = b * G3x + (i + 3) * G2x + (j + 3) * Gx + (k + 3);
    const float2* __restrict__ p0 = g_combo2 + src;
    const float2* __restrict__ p1 = g_combo2 + SHIFT + src;

    float4 go, ao;
#pragma unroll
    for (int u = 0; u < 4; u++) {
        float2 c0 = __ldg(p0 + u);
        float2 c1 = __ldg(p1 + u);
        float g = c0.x + c1.x;
        float a = c0.y + c1.y;
        float v = (a > 0.0f) ? __fdividef(g, a + 1e-9f) : g;
        if (u == 0) { go.x = v; ao.x = a; }
        if (u == 1) { go.y = v; ao.y = a; }
        if (u == 2) { go.z = v; ao.z = a; }
        if (u == 3) { go.w = v; ao.w = a; }
    }
    *reinterpret_cast<float4*>(out + o) = go;
    if (writeAcc) *reinterpret_cast<float4*>(out + tot + o) = ao;
}

// ---------------------------------------------------------------------------
extern "C" void kernel_launch(void* const* d_in, const int* in_sizes, int n_in,
                              void* d_out, int out_size) {
    const float* points = (const float*)d_in[0];
    const float* dens   = (const float*)d_in[1];
    const float* bbox   = (const float*)d_in[2];
    float* out = (float*)d_out;

    int total = in_sizes[1];              // B * N
    int B = total / 131072;
    if (B < 1) B = 1;
    if (B > MAXB) B = MAXB;
    int Npb = total / B;

    int writeAcc = (out_size >= 2 * B * CROPV) ? 1 : 0;

    // 1) zero readable scratch (i-trimmed: out-of-crop i-shells never read)
    {
        int zThreads = 2 * B * (ZLEN / 2);   // 4 slices x float4 count (B=2)
        int tpb = 256;
        splat_zero_kernel<<<(zThreads + tpb - 1) / tpb, tpb>>>(B);
    }
    // 2) scatter
    {
        int tpb = 256;
        splat_scatter_kernel<<<(total + tpb - 1) / tpb, tpb>>>(points, dens, bbox,
                                                               total, Npb);
    }
    // 3) normalize + crop + write
    {
        int tot4 = (B * CROPV) >> 2;
        int tpb = 256;
        splat_finalize_kernel<<<(tot4 + tpb - 1) / tpb, tpb>>>(out, B, writeAcc);
    }
}